// round 14
// baseline (speedup 1.0000x reference)
#include <cuda_runtime.h>
#include <cuda_bf16.h>
#include <cuda_fp16.h>
#include <cstdint>

// ---------------------------------------------------------------------------
// ManifoldWorms pipeline, round 13 (= round 12 resubmit, dead code removed):
//   occ-3 dist, 2-product sims, vector gpart
//   Output flat f32: exit_outputs(512x1024) | garbage(1024) | units(64x1024)
// ---------------------------------------------------------------------------

#define N_Q   576
#define N_QP  640
#define N_I   8192
#define N_E   128
#define N_C   1024
#define N_U   64
#define N_O   512

// ------------------------- device scratch ----------------------------------
__device__ float   g_tinv[N_I];
__device__ __half  g_Qhi[N_QP * N_E];
__device__ __half  g_Thi[N_I * N_E];
__device__ __half  g_Tlo[N_I * N_E];
__device__ __half  g_A [N_QP * N_I];
__device__ __half  g_B1[N_C * N_I];
__device__ float   g_cs[8 * N_I];
__device__ float   g_unit_in[N_U * N_C];
__device__ float   g_gpart[512 * N_C];
__device__ float   g_partA[16 * 128 * N_C];   // 8 MB  (q-tile 0, KSPLIT 16)
__device__ float   g_partB[8 * 512 * N_C];    // 16 MB (q-tiles 1..4, KSPLIT 8)
__device__ float   g_upart[8][N_U][N_C];

// ------------------------- helpers -----------------------------------------
__device__ __forceinline__ uint32_t smem_u32(const void* p) {
    uint32_t a;
    asm("{ .reg .u64 t; cvta.to.shared.u64 t, %1; cvt.u32.u64 %0, t; }"
        : "=r"(a) : "l"(p));
    return a;
}
__device__ __forceinline__ void cp16(uint32_t dst, const void* src) {
    asm volatile("cp.async.cg.shared.global [%0], [%1], 16;\n"
                 :: "r"(dst), "l"(src) : "memory");
}
#define CP_COMMIT() asm volatile("cp.async.commit_group;\n" ::: "memory")
#define CP_WAIT(n)  asm volatile("cp.async.wait_group %0;\n" :: "n"(n) : "memory")

__device__ __forceinline__ void ldm_x4(uint32_t* r, uint32_t addr) {
    asm volatile("ldmatrix.sync.aligned.m8n8.x4.shared.b16 {%0,%1,%2,%3}, [%4];"
        : "=r"(r[0]), "=r"(r[1]), "=r"(r[2]), "=r"(r[3]) : "r"(addr));
}
__device__ __forceinline__ void mma_f16(float* c, const uint32_t* a,
                                        uint32_t b0, uint32_t b1) {
    asm volatile(
        "mma.sync.aligned.m16n8k16.row.col.f32.f16.f16.f32 "
        "{%0,%1,%2,%3}, {%4,%5,%6,%7}, {%8,%9}, {%0,%1,%2,%3};\n"
        : "+f"(c[0]), "+f"(c[1]), "+f"(c[2]), "+f"(c[3])
        : "r"(a[0]), "r"(a[1]), "r"(a[2]), "r"(a[3]), "r"(b0), "r"(b1));
}

// ---------------------------------------------------------------------------
// K0 (prep1): queries -> normalized fp16;  tails -> tinv + fp16 hi/lo
// ---------------------------------------------------------------------------
__global__ void k_prep1(const float* __restrict__ unit_heads,
                        const float* __restrict__ exit_heads,
                        const float* __restrict__ tails) {
    if (blockIdx.x < N_Q) {
        int row = blockIdx.x;
        const float* src = (row < N_U) ? (unit_heads + row * N_E)
                                       : (exit_heads + (row - N_U) * N_E);
        float v = src[threadIdx.x];
        float s = v * v;
        #pragma unroll
        for (int o = 16; o; o >>= 1) s += __shfl_xor_sync(0xffffffffu, s, o);
        __shared__ float ws[4];
        if ((threadIdx.x & 31) == 0) ws[threadIdx.x >> 5] = s;
        __syncthreads();
        float q = v * rsqrtf(ws[0] + ws[1] + ws[2] + ws[3]);
        g_Qhi[row * N_E + threadIdx.x] = __float2half(q);
    } else {
        int warp = threadIdx.x >> 5, lane = threadIdx.x & 31;
        int row = (blockIdx.x - N_Q) * 4 + warp;
        const float* r = tails + row * N_E;
        float vv[4];
        float s = 0.f;
        #pragma unroll
        for (int i = 0; i < 4; i++) { vv[i] = r[lane + 32 * i]; s += vv[i] * vv[i]; }
        #pragma unroll
        for (int o = 16; o; o >>= 1) s += __shfl_xor_sync(0xffffffffu, s, o);
        if (lane == 0) g_tinv[row] = rsqrtf(s);
        #pragma unroll
        for (int i = 0; i < 4; i++) {
            __half h = __float2half(vv[i]);
            g_Thi[row * N_E + lane + 32 * i] = h;
            g_Tlo[row * N_E + lane + 32 * i] = __float2half(vv[i] - __half2float(h));
        }
    }
}

// ---------------------------------------------------------------------------
// K1 (sims): influences = relu((Qn @ T^T) * tinv)  via 2-product fp16 mma
//     CTA tile M=64 N=128, K=128 in 2 chunks; 8 warps (2x4), 32x32 tiles
// ---------------------------------------------------------------------------
#define SIMS_QB   9216
#define SIMS_TB   18432
#define SIMS_THI  SIMS_QB
#define SMEM_SIMS (SIMS_QB + 2 * SIMS_TB)   // 46080

__global__ void __launch_bounds__(256, 2)
k_sims_mma() {
    extern __shared__ uint16_t sh[];
    uint32_t sbase = smem_u32(sh);
    int tid  = threadIdx.x;
    int wid  = tid >> 5, lane = tid & 31;
    int wm   = wid & 1, wn = wid >> 1;
    int g    = lane >> 2, c = lane & 3;
    int l15  = lane & 15;
    int lhalf = (lane >> 4) << 4;

    int q0 = blockIdx.x * 64;
    int j0 = blockIdx.y * 128;

    const char* Qh = (const char*)g_Qhi;
    const char* Th = (const char*)g_Thi;
    const char* Tl = (const char*)g_Tlo;

    float acc[2][4][4] = {};

    for (int ch = 0; ch < 2; ch++) {
        int k0 = ch * 64;
        // Q tile: 64 rows x 8 segs = 512 cp16 -> 2 per thread
        #pragma unroll
        for (int i = 0; i < 2; i++) {
            int u = tid + i * 256;
            int row = u >> 3, seg = u & 7;
            uint32_t d = sbase + row * 144 + seg * 16;
            long off = ((long)(q0 + row) * N_E + k0 + seg * 8) << 1;
            cp16(d, Qh + off);
        }
        // T tiles: 128 rows x 8 segs = 1024 cp16 each (hi, lo)
        #pragma unroll
        for (int i = 0; i < 4; i++) {
            int u = tid + i * 256;
            int row = u >> 3, seg = u & 7;
            uint32_t d = sbase + SIMS_THI + row * 144 + seg * 16;
            long off = ((long)(j0 + row) * N_E + k0 + seg * 8) << 1;
            cp16(d, Th + off);
            cp16(d + SIMS_TB, Tl + off);
        }
        CP_COMMIT();
        CP_WAIT(0);
        __syncthreads();

        uint32_t aRow0 = sbase + (wm * 32 + l15) * 144 + lhalf;
        uint32_t aRow1 = aRow0 + 16 * 144;
        uint32_t bRow0 = sbase + SIMS_THI + (wn * 32 + l15) * 144 + lhalf;
        uint32_t bRow1 = bRow0 + 16 * 144;

        #pragma unroll
        for (int kk = 0; kk < 4; kk++) {
            int cb = kk * 32;
            uint32_t ah[2][4], bhA[4], bhB[4], blA[4], blB[4];
            ldm_x4(ah[0], aRow0 + cb);
            ldm_x4(ah[1], aRow1 + cb);
            ldm_x4(bhA, bRow0 + cb);
            ldm_x4(bhB, bRow1 + cb);
            ldm_x4(blA, bRow0 + SIMS_TB + cb);
            ldm_x4(blB, bRow1 + SIMS_TB + cb);
            #pragma unroll
            for (int mi = 0; mi < 2; mi++) {
                mma_f16(acc[mi][0], ah[mi], bhA[0], bhA[2]);
                mma_f16(acc[mi][1], ah[mi], bhA[1], bhA[3]);
                mma_f16(acc[mi][2], ah[mi], bhB[0], bhB[2]);
                mma_f16(acc[mi][3], ah[mi], bhB[1], bhB[3]);
                mma_f16(acc[mi][0], ah[mi], blA[0], blA[2]);
                mma_f16(acc[mi][1], ah[mi], blA[1], blA[3]);
                mma_f16(acc[mi][2], ah[mi], blB[0], blB[2]);
                mma_f16(acc[mi][3], ah[mi], blB[1], blB[3]);
            }
        }
        __syncthreads();
    }

    #pragma unroll
    for (int mi = 0; mi < 2; mi++) {
        int m = q0 + wm * 32 + mi * 16 + g;
        #pragma unroll
        for (int ni = 0; ni < 4; ni++) {
            int j = j0 + wn * 32 + ni * 8 + 2 * c;
            float t0 = g_tinv[j], t1 = g_tinv[j + 1];
            float v0 = acc[mi][ni][0] * t0; v0 = v0 > 0.f ? v0 : 0.f;
            float v1 = acc[mi][ni][1] * t1; v1 = v1 > 0.f ? v1 : 0.f;
            float v2 = acc[mi][ni][2] * t0; v2 = v2 > 0.f ? v2 : 0.f;
            float v3 = acc[mi][ni][3] * t1; v3 = v3 > 0.f ? v3 : 0.f;
            *(__half2*)(g_A + (size_t)m * N_I + j)       = __floats2half2_rn(v0, v1);
            *(__half2*)(g_A + (size_t)(m + 8) * N_I + j) = __floats2half2_rn(v2, v3);
        }
    }
}

// ---------------------------------------------------------------------------
// K2 (prep2): state transpose -> B1 [C][K] fp16
// ---------------------------------------------------------------------------
__global__ void k_prep2(const float* __restrict__ state) {
    __shared__ float t[32][33];
    int kb = blockIdx.x & 255;
    int cb = blockIdx.x >> 8;
    int k0 = kb * 32, c0 = cb * 32;
    int tx = threadIdx.x & 31, ty = threadIdx.x >> 5;
    #pragma unroll
    for (int i = 0; i < 4; i++)
        t[ty + 8 * i][tx] = state[(size_t)(k0 + ty + 8 * i) * N_C + c0 + tx];
    __syncthreads();
    #pragma unroll
    for (int i = 0; i < 4; i++) {
        int c = c0 + ty + 8 * i;
        int k = k0 + tx;
        g_B1[c * N_I + k] = __float2half(t[tx][ty + 8 * i]);
    }
}

// ---------------------------------------------------------------------------
// K3 (dist): distributed = influences @ state; single-product fp16 mma
//     CTA 128x64, occ 3; distA (q-tile 0, Z=16) / distB (tiles 1-4, Z=8)
// ---------------------------------------------------------------------------
#define KC       64
#define DIST_AB  18432
#define DIST_BB  9216
#define STAGEB   (DIST_AB + DIST_BB)       // 27648
#define SMEM_DIST (2 * STAGEB)             // 55296

__global__ void __launch_bounds__(256, 3)
k_dist_mma(int q_tile_off, int use_b) {
    extern __shared__ uint16_t sh[];
    uint32_t sbase = smem_u32(sh);

    int tid  = threadIdx.x;
    int wid  = tid >> 5, lane = tid & 31;
    int wm   = wid >> 1, wn = wid & 1;
    int g    = lane >> 2, c = lane & 3;
    int l15  = lane & 15;
    int lhalf = (lane >> 4) << 4;

    int q0 = (blockIdx.x + q_tile_off) * 128;
    int c0 = blockIdx.y * 64;
    int kspan = N_I / gridDim.z;
    int kbase = blockIdx.z * kspan;
    int NCHUNK = kspan / KC;

    const char* Aa = (const char*)g_A;
    const char* B1 = (const char*)g_B1;

    float acc[2][4][4] = {};

    auto load_chunk = [&](int it) {
        int k0 = kbase + it * KC;
        uint32_t buf = sbase + (it & 1) * STAGEB;
        #pragma unroll
        for (int i = 0; i < 4; i++) {
            int u   = tid + i * 256;
            int row = u >> 3, seg = u & 7;
            long aoff = ((long)(q0 + row) * N_I + k0 + seg * 8) << 1;
            cp16(buf + row * 144 + seg * 16, Aa + aoff);
        }
        #pragma unroll
        for (int i = 0; i < 2; i++) {
            int u   = tid + i * 256;
            int row = u >> 3, seg = u & 7;
            long boff = ((long)(c0 + row) * N_I + k0 + seg * 8) << 1;
            cp16(buf + DIST_AB + row * 144 + seg * 16, B1 + boff);
        }
    };

    load_chunk(0);
    CP_COMMIT();

    for (int it = 0; it < NCHUNK; it++) {
        if (it + 1 < NCHUNK) { load_chunk(it + 1); CP_COMMIT(); CP_WAIT(1); }
        else                 { CP_WAIT(0); }
        __syncthreads();

        uint32_t buf = sbase + (it & 1) * STAGEB;
        uint32_t aRow0 = buf + (wm * 32 + l15) * 144 + lhalf;
        uint32_t aRow1 = aRow0 + 16 * 144;
        uint32_t bRow0 = buf + DIST_AB + (wn * 32 + l15) * 144 + lhalf;
        uint32_t bRow1 = bRow0 + 16 * 144;

        #pragma unroll
        for (int kk = 0; kk < 4; kk++) {
            int cb = kk * 32;
            uint32_t a[2][4], bA[4], bB[4];
            ldm_x4(a[0], aRow0 + cb);
            ldm_x4(a[1], aRow1 + cb);
            ldm_x4(bA, bRow0 + cb);
            ldm_x4(bB, bRow1 + cb);
            #pragma unroll
            for (int mi = 0; mi < 2; mi++) {
                mma_f16(acc[mi][0], a[mi], bA[0], bA[2]);
                mma_f16(acc[mi][1], a[mi], bA[1], bA[3]);
                mma_f16(acc[mi][2], a[mi], bB[0], bB[2]);
                mma_f16(acc[mi][3], a[mi], bB[1], bB[3]);
            }
        }
        __syncthreads();
    }

    float* part = (use_b ? g_partB : g_partA)
                + (size_t)blockIdx.z * gridDim.x * 128 * N_C;
    #pragma unroll
    for (int mi = 0; mi < 2; mi++) {
        int m0 = blockIdx.x * 128 + wm * 32 + mi * 16 + g;
        #pragma unroll
        for (int ni = 0; ni < 4; ni++) {
            int n0 = c0 + wn * 32 + ni * 8 + 2 * c;
            part[(size_t)m0 * N_C + n0]           = acc[mi][ni][0];
            part[(size_t)m0 * N_C + n0 + 1]       = acc[mi][ni][1];
            part[(size_t)(m0 + 8) * N_C + n0]     = acc[mi][ni][2];
            part[(size_t)(m0 + 8) * N_C + n0 + 1] = acc[mi][ni][3];
        }
    }
}

// ---------------------------------------------------------------------------
// K4: colsum partials over q chunks
// ---------------------------------------------------------------------------
__global__ void k_colsum_part() {
    int j = blockIdx.x * 256 + threadIdx.x;
    int qc = blockIdx.y;
    float s = 0.f;
    for (int q = qc * 72; q < (qc + 1) * 72; q++)
        s += __half2float(g_A[(size_t)q * N_I + j]);
    g_cs[qc * N_I + j] = s;
}

// ---------------------------------------------------------------------------
// K5a: reduce distA partials for unit rows 0..63 -> g_unit_in (float4)
// ---------------------------------------------------------------------------
__global__ void k_redU() {
    int m = blockIdx.x;
    int n4 = threadIdx.x;
    float4 s = make_float4(0.f, 0.f, 0.f, 0.f);
    #pragma unroll
    for (int ks = 0; ks < 16; ks++) {
        float4 p = ((const float4*)(g_partA + ((size_t)ks * 128 + m) * N_C))[n4];
        s.x += p.x; s.y += p.y; s.z += p.z; s.w += p.w;
    }
    ((float4*)(g_unit_in + m * N_C))[n4] = s;
}

// K5b: reduce exit rows 64..575 -> out_exit (float4)
__global__ void k_redE(float* __restrict__ out_exit) {
    int m = blockIdx.x + N_U;
    int n4 = threadIdx.x;
    float4 s = make_float4(0.f, 0.f, 0.f, 0.f);
    if (m < 128) {
        #pragma unroll
        for (int ks = 0; ks < 16; ks++) {
            float4 p = ((const float4*)(g_partA + ((size_t)ks * 128 + m) * N_C))[n4];
            s.x += p.x; s.y += p.y; s.z += p.z; s.w += p.w;
        }
    } else {
        int lm = m - 128;
        #pragma unroll
        for (int ks = 0; ks < 8; ks++) {
            float4 p = ((const float4*)(g_partB + ((size_t)ks * 512 + lm) * N_C))[n4];
            s.x += p.x; s.y += p.y; s.z += p.z; s.w += p.w;
        }
    }
    ((float4*)(out_exit + (size_t)(m - N_U) * N_C))[n4] = s;
}

// ---------------------------------------------------------------------------
// K6: garbage partials (512 chunks of 16 rows, float4); w inline from g_cs
// ---------------------------------------------------------------------------
__global__ void k_gpart_w(const float* __restrict__ state) {
    int jc = blockIdx.x;
    int tid = threadIdx.x;
    __shared__ float ws[16];
    if (tid < 16) {
        int j = jc * 16 + tid;
        float s = 0.f;
        #pragma unroll
        for (int p = 0; p < 8; p++) s += g_cs[p * N_I + j];
        ws[tid] = 1.0f - s;
    }
    __syncthreads();
    float4 acc = make_float4(0.f, 0.f, 0.f, 0.f);
    #pragma unroll
    for (int r = 0; r < 16; r++) {
        float wj = ws[r];
        float4 v = ((const float4*)(state + (size_t)(jc * 16 + r) * N_C))[tid];
        acc.x += wj * v.x; acc.y += wj * v.y;
        acc.z += wj * v.z; acc.w += wj * v.w;
    }
    ((float4*)(g_gpart + (size_t)jc * N_C))[tid] = acc;
}

// ---------------------------------------------------------------------------
// K7: units partials: grid (64 u, 8 c-slices), contiguous 512KB/blk stream
// ---------------------------------------------------------------------------
__global__ void __launch_bounds__(256) k_units_part(const float* __restrict__ W) {
    int u = blockIdx.x, sl = blockIdx.y;
    int c0 = sl * 128;
    __shared__ float sin[128];
    if (threadIdx.x < 128) sin[threadIdx.x] = g_unit_in[u * N_C + c0 + threadIdx.x];
    __syncthreads();
    const float4* Wu = (const float4*)(W + ((size_t)u * N_C + c0) * N_C) + threadIdx.x;
    float4 acc = make_float4(0.f, 0.f, 0.f, 0.f);
    #pragma unroll 4
    for (int c = 0; c < 128; c++) {
        float4 w4 = Wu[(size_t)c * (N_C / 4)];
        float s = sin[c];
        acc.x += s * w4.x; acc.y += s * w4.y;
        acc.z += s * w4.z; acc.w += s * w4.w;
    }
    ((float4*)&g_upart[sl][u][0])[threadIdx.x] = acc;
}

// ---------------------------------------------------------------------------
// K8: units finalize (blocks 0..63) + garbage reduce (blocks 64..67)
// ---------------------------------------------------------------------------
__global__ void k_fin(const float* __restrict__ bias,
                      float* __restrict__ out_units,
                      float* __restrict__ out_g) {
    if (blockIdx.x < N_U) {
        int u = blockIdx.x;
        int d4 = threadIdx.x;
        float4 s = make_float4(0.f, 0.f, 0.f, 0.f);
        #pragma unroll
        for (int sl = 0; sl < 8; sl++) {
            float4 p = ((const float4*)&g_upart[sl][u][0])[d4];
            s.x += p.x; s.y += p.y; s.z += p.z; s.w += p.w;
        }
        float4 b4 = ((const float4*)(bias + u * N_C))[d4];
        float4 in4 = ((const float4*)(g_unit_in + u * N_C))[d4];
        float hx = s.x + b4.x, hy = s.y + b4.y, hz = s.z + b4.z, hw = s.w + b4.w;
        float4 o;
        o.x = in4.x + (hx > 0.f ? hx : 0.f);
        o.y = in4.y + (hy > 0.f ? hy : 0.f);
        o.z = in4.z + (hz > 0.f ? hz : 0.f);
        o.w = in4.w + (hw > 0.f ? hw : 0.f);
        ((float4*)(out_units + u * N_C))[d4] = o;
    } else {
        int c = (blockIdx.x - N_U) * 256 + threadIdx.x;
        float s = 0.f;
        for (int p = 0; p < 512; p++) s += g_gpart[(size_t)p * N_C + c];
        out_g[c] = s;
    }
}

// ---------------------------------------------------------------------------
extern "C" void kernel_launch(void* const* d_in, const int* in_sizes, int n_in,
                              void* d_out, int out_size) {
    const float* state       = (const float*)d_in[0];
    const float* input_tails = (const float*)d_in[1];
    const float* exit_heads  = (const float*)d_in[2];
    const float* unit_heads  = (const float*)d_in[3];
    const float* unit_W      = (const float*)d_in[5];
    const float* unit_b      = (const float*)d_in[6];

    float* out       = (float*)d_out;
    float* out_exit  = out;
    float* out_garb  = out + N_O * N_C;
    float* out_units = out + N_O * N_C + N_C;

    static cudaStream_t s1 = nullptr, s2 = nullptr, s3 = nullptr;
    static cudaEvent_t evF = nullptr, evB1, evA, evRU, evU, evG;
    if (!s1) {
        cudaStreamCreateWithFlags(&s1, cudaStreamNonBlocking);
        cudaStreamCreateWithFlags(&s2, cudaStreamNonBlocking);
        cudaStreamCreateWithFlags(&s3, cudaStreamNonBlocking);
        cudaEventCreateWithFlags(&evF,  cudaEventDisableTiming);
        cudaEventCreateWithFlags(&evB1, cudaEventDisableTiming);
        cudaEventCreateWithFlags(&evA,  cudaEventDisableTiming);
        cudaEventCreateWithFlags(&evRU, cudaEventDisableTiming);
        cudaEventCreateWithFlags(&evU,  cudaEventDisableTiming);
        cudaEventCreateWithFlags(&evG,  cudaEventDisableTiming);
    }

    cudaFuncSetAttribute(k_dist_mma,
                         cudaFuncAttributeMaxDynamicSharedMemorySize, SMEM_DIST);
    cudaFuncSetAttribute(k_sims_mma,
                         cudaFuncAttributeMaxDynamicSharedMemorySize, SMEM_SIMS);

    // ---- fork s1: prep2 (depends only on state) ----
    cudaEventRecord(evF, 0);
    cudaStreamWaitEvent(s1, evF, 0);
    k_prep2<<<8192, 256, 0, s1>>>(state);
    cudaEventRecord(evB1, s1);

    // ---- main chain: prep1 -> sims ----
    k_prep1<<<N_Q + N_I / 4, 128>>>(unit_heads, exit_heads, input_tails);
    k_sims_mma<<<dim3(N_QP / 64, N_I / 128), 256, SMEM_SIMS>>>();
    cudaEventRecord(evA, 0);

    // ---- fork s2: colsum + garbage partials ----
    cudaStreamWaitEvent(s2, evA, 0);
    k_colsum_part<<<dim3(N_I / 256, 8), 256, 0, s2>>>();
    k_gpart_w<<<512, 256, 0, s2>>>(state);
    cudaEventRecord(evG, s2);

    // ---- distA (q-tile 0) + unit reduce ----
    cudaStreamWaitEvent(0, evB1, 0);
    k_dist_mma<<<dim3(1, 16, 16), 256, SMEM_DIST>>>(0, 0);
    k_redU<<<N_U, 256>>>();
    cudaEventRecord(evRU, 0);

    // ---- fork s3: units stream overlaps distB ----
    cudaStreamWaitEvent(s3, evRU, 0);
    k_units_part<<<dim3(N_U, 8), 256, 0, s3>>>(unit_W);
    cudaEventRecord(evU, s3);

    // ---- distB (q-tiles 1..4) + exit reduce ----
    k_dist_mma<<<dim3(4, 16, 8), 256, SMEM_DIST>>>(1, 1);
    k_redE<<<N_Q - N_U, 256>>>(out_exit);

    // ---- join, finalize ----
    cudaStreamWaitEvent(0, evU, 0);
    cudaStreamWaitEvent(0, evG, 0);
    k_fin<<<N_U + N_C / 256, 256>>>(unit_b, out_units, out_garb);
}